// round 9
// baseline (speedup 1.0000x reference)
#include <cuda_runtime.h>
#include <cuda_bf16.h>

// ---------------------------------------------------------------------------
// SSIM (11x11 Gaussian, sigma=1.5, SAME zero padding) over 32x3x512x512 fp32.
// R8: 32x64 tile with 512-thread CTA keeping R6's per-thread shape
//     (4-row blocking, 20 accumulator regs), float4-packed H (2 LDS/k in the
//     vertical pass), STS.128 stores, interior fast path, scalar FFMA-imm.
// Deterministic two-stage reduction.
// ---------------------------------------------------------------------------

#define IMG_H 512
#define IMG_W 512
#define N_PLANES 96            // 32 * 3
#define TILE_X 32
#define TILE_Y 64
#define HALO 5
#define LOADX 42               // TILE_X + 2*HALO
#define LOADY 74               // TILE_Y + 2*HALO
#define PITCH 44               // LOADX padded for 16B float4 alignment
#define NTHR 512
#define NBLK_X (IMG_W / TILE_X)   // 16
#define NBLK_Y (IMG_H / TILE_Y)   // 8
#define NPART (NBLK_X * NBLK_Y * N_PLANES)  // 12288
#define NPART2 48
#define NPIX (32.0 * 3.0 * 512.0 * 512.0)   // 25165824

#define C1F 0.0001f            // (0.01)^2
#define C2F 0.0009f            // (0.03)^2

// Gaussian taps as compile-time constants -> FFMA-imm in SASS.
__device__ constexpr double G0 = 0.003865920;   // exp(-25/4.5)
__device__ constexpr double G1 = 0.028565467;   // exp(-16/4.5)
__device__ constexpr double G2 = 0.135335283;   // exp(-9/4.5)
__device__ constexpr double G3 = 0.411111966;   // exp(-4/4.5)
__device__ constexpr double G4 = 0.800737403;   // exp(-1/4.5)
__device__ constexpr double G5 = 1.0;
__device__ constexpr double GS = G5 + 2.0 * (G0 + G1 + G2 + G3 + G4);
__device__ constexpr float W11[11] = {
    (float)(G0 / GS), (float)(G1 / GS), (float)(G2 / GS), (float)(G3 / GS),
    (float)(G4 / GS), (float)(G5 / GS), (float)(G4 / GS), (float)(G3 / GS),
    (float)(G2 / GS), (float)(G1 / GS), (float)(G0 / GS)};

__device__ float g_partial[NPART];
__device__ float g_partial2[NPART2];

// smem layout (floats):
//   Q:     [2][LOADY][PITCH]                        = 6512
//   H0123: [LOADY][TILE_X][4] (mu1,mu2,ex2,ey2)     = 9472
//   H4:    [LOADY][TILE_X]    (exy)                 = 2368
#define SMEM_Q_FLOATS (2 * LOADY * PITCH)
#define SMEM_H0123_OFF (SMEM_Q_FLOATS)
#define SMEM_H4_OFF    (SMEM_H0123_OFF + LOADY * TILE_X * 4)
#define SMEM_FLOATS    (SMEM_H4_OFF + LOADY * TILE_X)
#define SMEM_BYTES     (SMEM_FLOATS * 4)   // 73408 B -> 3 CTAs/SM (48 warps)

__global__ __launch_bounds__(NTHR, 3) void ssim_tile_kernel(
    const float* __restrict__ img1, const float* __restrict__ img2)
{
    extern __shared__ float smem[];
    float* Q     = smem;
    float* H0123 = smem + SMEM_H0123_OFF;
    float* H4    = smem + SMEM_H4_OFF;
    __shared__ float red[NTHR];

#define QQ(q, r, c) Q[((q) * LOADY + (r)) * PITCH + (c)]

    const int tid = threadIdx.x;
    const int plane = blockIdx.z;
    const int ty0 = blockIdx.y * TILE_Y - HALO;
    const int tx0 = blockIdx.x * TILE_X - HALO;
    const float* p1 = img1 + (size_t)plane * IMG_H * IMG_W;
    const float* p2 = img2 + (size_t)plane * IMG_H * IMG_W;

    // ---- Stage 1: load halo tile (zero padded), interior fast path ----
    const bool interior = (ty0 >= 0) & (ty0 + LOADY <= IMG_H) &
                          (tx0 >= 0) & (tx0 + LOADX <= IMG_W);
    if (interior) {
        const float* b1 = p1 + ty0 * IMG_W + tx0;
        const float* b2 = p2 + ty0 * IMG_W + tx0;
        for (int i = tid; i < LOADY * LOADX; i += NTHR) {
            int r = i / LOADX, c = i - r * LOADX;
            int gidx = r * IMG_W + c;
            QQ(0, r, c) = b1[gidx];
            QQ(1, r, c) = b2[gidx];
        }
    } else {
        for (int i = tid; i < LOADY * LOADX; i += NTHR) {
            int r = i / LOADX, c = i - r * LOADX;
            int gy = ty0 + r, gx = tx0 + c;
            float a = 0.f, b = 0.f;
            if (gy >= 0 && gy < IMG_H && gx >= 0 && gx < IMG_W) {
                int gidx = gy * IMG_W + gx;
                a = p1[gidx];
                b = p2[gidx];
            }
            QQ(0, r, c) = a;
            QQ(1, r, c) = b;
        }
    }
    __syncthreads();

    // ---- Stage 2: horizontal 11-tap pass over 5 moments, 4-col blocking ----
    // 74 rows x 8 col-groups = 592 groups over 512 threads.
    for (int gi = tid; gi < LOADY * 8; gi += NTHR) {
        int r = gi >> 3;
        int c0 = (gi & 7) * 4;     // outputs c0..c0+3, inputs c0..c0+13
        float av[16], bv[16];
        {
            const float4* sa = (const float4*)&QQ(0, r, c0);
            const float4* sb = (const float4*)&QQ(1, r, c0);
#pragma unroll
            for (int t = 0; t < 4; t++) {
                float4 fa = sa[t], fb = sb[t];
                av[4 * t + 0] = fa.x; av[4 * t + 1] = fa.y;
                av[4 * t + 2] = fa.z; av[4 * t + 3] = fa.w;
                bv[4 * t + 0] = fb.x; bv[4 * t + 1] = fb.y;
                bv[4 * t + 2] = fb.z; bv[4 * t + 3] = fb.w;
            }
        }
        float acc[5][4];
#pragma unroll
        for (int qi = 0; qi < 5; qi++)
#pragma unroll
            for (int j = 0; j < 4; j++) acc[qi][j] = 0.f;

#pragma unroll
        for (int k = 0; k < 14; k++) {
            float a = av[k], b = bv[k];
            float aa = a * a, bb = b * b, ab = a * b;
#pragma unroll
            for (int j = 0; j < 4; j++) {
                const int wi = k - j;
                if (wi >= 0 && wi < 11) {
                    acc[0][j] = fmaf(W11[wi], a,  acc[0][j]);
                    acc[1][j] = fmaf(W11[wi], b,  acc[1][j]);
                    acc[2][j] = fmaf(W11[wi], aa, acc[2][j]);
                    acc[3][j] = fmaf(W11[wi], bb, acc[3][j]);
                    acc[4][j] = fmaf(W11[wi], ab, acc[4][j]);
                }
            }
        }
        // Packed stores: one float4 (mu1,mu2,ex2,ey2) per output col + exy row.
        {
            float4* d = (float4*)&H0123[(r * TILE_X + c0) * 4];
#pragma unroll
            for (int j = 0; j < 4; j++)
                d[j] = make_float4(acc[0][j], acc[1][j], acc[2][j], acc[3][j]);
            *(float4*)&H4[r * TILE_X + c0] =
                make_float4(acc[4][0], acc[4][1], acc[4][2], acc[4][3]);
        }
    }
    __syncthreads();

    // ---- Stage 3: vertical 11-tap pass, LDS.128 packed loads, 4-row blocking ----
    // 512 threads = 32 cols x 16 row-groups, each group = 4 output rows.
    const int c = tid & 31;
    const int r0 = (tid >> 5) * 4;   // output rows r0..r0+3, inputs r0..r0+13
    float acc[5][4];
#pragma unroll
    for (int qi = 0; qi < 5; qi++)
#pragma unroll
        for (int j = 0; j < 4; j++) acc[qi][j] = 0.f;

#pragma unroll
    for (int k = 0; k < 14; k++) {
        float4 m = *(const float4*)&H0123[((r0 + k) * TILE_X + c) * 4];
        float vxy = H4[(r0 + k) * TILE_X + c];
#pragma unroll
        for (int j = 0; j < 4; j++) {
            const int wi = k - j;
            if (wi >= 0 && wi < 11) {
                acc[0][j] = fmaf(W11[wi], m.x, acc[0][j]);
                acc[1][j] = fmaf(W11[wi], m.y, acc[1][j]);
                acc[2][j] = fmaf(W11[wi], m.z, acc[2][j]);
                acc[3][j] = fmaf(W11[wi], m.w, acc[3][j]);
                acc[4][j] = fmaf(W11[wi], vxy, acc[4][j]);
            }
        }
    }

    float local = 0.f;
#pragma unroll
    for (int j = 0; j < 4; j++) {
        float mu1 = acc[0][j], mu2 = acc[1][j];
        float ex2 = acc[2][j], ey2 = acc[3][j], exy = acc[4][j];
        float mu1s = mu1 * mu1, mu2s = mu2 * mu2, mu12 = mu1 * mu2;
        float s1q = fmaxf(ex2 - mu1s, 0.f);
        float s2q = fmaxf(ey2 - mu2s, 0.f);
        float s12 = exy - mu12;
        float sp = sqrtf(s1q * s2q);         // == s1*s2
        float num = (2.f * mu12 + C1F) * (2.f * sp + C2F) * (s12 + 0.5f * C2F);
        float den = (mu1s + mu2s + C1F) * (s1q + s2q + C2F) * (sp + 0.5f * C2F);
        local += __fdividef(num, den);
    }

    // ---- Block reduction (fixed-order tree: deterministic) ----
    red[tid] = local;
    __syncthreads();
#pragma unroll
    for (int s = NTHR / 2; s > 0; s >>= 1) {
        if (tid < s) red[tid] += red[tid + s];
        __syncthreads();
    }
    if (tid == 0) {
        int bid = (blockIdx.z * NBLK_Y + blockIdx.y) * NBLK_X + blockIdx.x;
        g_partial[bid] = red[0];
    }
#undef QQ
}

// Stage A: 48 blocks, each sums 256 contiguous partials (deterministic tree).
__global__ __launch_bounds__(256) void ssim_reduceA_kernel()
{
    __shared__ float red[256];
    const int tid = threadIdx.x;
    red[tid] = g_partial[blockIdx.x * 256 + tid];
    __syncthreads();
#pragma unroll
    for (int s = 128; s > 0; s >>= 1) {
        if (tid < s) red[tid] += red[tid + s];
        __syncthreads();
    }
    if (tid == 0) g_partial2[blockIdx.x] = red[0];
}

// Stage B: single block sums 48 values in double, normalizes.
__global__ __launch_bounds__(64) void ssim_reduceB_kernel(float* __restrict__ out)
{
    __shared__ double red[64];
    const int tid = threadIdx.x;
    red[tid] = (tid < NPART2) ? (double)g_partial2[tid] : 0.0;
    __syncthreads();
#pragma unroll
    for (int st = 32; st > 0; st >>= 1) {
        if (tid < st) red[tid] += red[tid + st];
        __syncthreads();
    }
    if (tid == 0) out[0] = (float)(red[0] / NPIX);
}

extern "C" void kernel_launch(void* const* d_in, const int* in_sizes, int n_in,
                              void* d_out, int out_size)
{
    const float* img1 = (const float*)d_in[0];
    const float* img2 = (const float*)d_in[1];
    // d_in[2] (window) unused: taps baked in as compile-time constants.
    float* out = (float*)d_out;

    static bool attr_done = false;
    if (!attr_done) {
        cudaFuncSetAttribute(ssim_tile_kernel,
                             cudaFuncAttributeMaxDynamicSharedMemorySize,
                             SMEM_BYTES);
        attr_done = true;
    }

    dim3 grid(NBLK_X, NBLK_Y, N_PLANES);
    ssim_tile_kernel<<<grid, NTHR, SMEM_BYTES>>>(img1, img2);
    ssim_reduceA_kernel<<<NPART2, 256>>>();
    ssim_reduceB_kernel<<<1, 64>>>(out);
}